// round 10
// baseline (speedup 1.0000x reference)
#include <cuda_runtime.h>
#include <cstdint>

// Problem constants
#define NB    8
#define NTOK  16384
#define NC    256
#define NWIN  2048    // B * (16x16 windows)
#define QKVW  768     // q(256) | k(256) | v(256)

// g_qkv channel dims stored PERMUTED within 8-groups:
// position p holds channel c(p) = (p&1)*4 + (p>>1)   (order 0,4,1,5,2,6,3,7)
__device__ float g_qkv[(size_t)NWIN * 64 * QKVW];
__device__ float g_wqk[512 * 256];     // rounded + permuted cols (rows natural)
__device__ float g_wv[256 * 256];
__device__ float g_wprojT[256 * 256];  // TRANSPOSED: [position][out_channel], rounded

// ---------------------------------------------------------------------------
__device__ __forceinline__ uint32_t f2tf(float f) {
    uint32_t u;
    asm("cvt.rna.tf32.f32 %0, %1;" : "=r"(u) : "f"(f));
    return u;
}
__device__ __forceinline__ float ftf(float f) {
    return __uint_as_float(f2tf(f));
}
__device__ __forceinline__ void mma_tf32(float c[4],
    uint32_t a0, uint32_t a1, uint32_t a2, uint32_t a3,
    uint32_t b0, uint32_t b1)
{
    asm volatile(
        "mma.sync.aligned.m16n8k8.row.col.f32.tf32.tf32.f32 "
        "{%0,%1,%2,%3},{%4,%5,%6,%7},{%8,%9},{%0,%1,%2,%3};"
        : "+f"(c[0]), "+f"(c[1]), "+f"(c[2]), "+f"(c[3])
        : "r"(a0), "r"(a1), "r"(a2), "r"(a3), "r"(b0), "r"(b1));
}
#define CPA16(dst, src) \
    asm volatile("cp.async.cg.shared.global [%0],[%1],16;" :: "r"(dst), "l"(src))
#define CP_COMMIT() asm volatile("cp.async.commit_group;")
#define CP_WAIT0()  asm volatile("cp.async.wait_group 0;" ::: "memory")

// ---------------------------------------------------------------------------
// Weights: round to tf32 + permute 8-groups. W_proj additionally transposed
// to position-major layout for the fused attention+proj kernel.
// ---------------------------------------------------------------------------
__global__ __launch_bounds__(256) void cvt_weights(
    const float* __restrict__ wqk, const float* __restrict__ wv,
    const float* __restrict__ wproj)
{
    const int t = blockIdx.x * 256 + threadIdx.x;
    const int off = t * 8;
    if (off < 131072) {
        const float* s = wqk + off;
        float* d = g_wqk + off;
        float4 v0 = ((const float4*)s)[0], v1 = ((const float4*)s)[1];
        ((float4*)d)[0] = make_float4(ftf(v0.x), ftf(v1.x), ftf(v0.y), ftf(v1.y));
        ((float4*)d)[1] = make_float4(ftf(v0.z), ftf(v1.z), ftf(v0.w), ftf(v1.w));
    } else if (off < 196608) {
        const float* s = wv + off - 131072;
        float* d = g_wv + off - 131072;
        float4 v0 = ((const float4*)s)[0], v1 = ((const float4*)s)[1];
        ((float4*)d)[0] = make_float4(ftf(v0.x), ftf(v1.x), ftf(v0.y), ftf(v1.y));
        ((float4*)d)[1] = make_float4(ftf(v0.z), ftf(v1.z), ftf(v0.w), ftf(v1.w));
    } else {
        const int loc = off - 196608;
        const int n = loc >> 8, p0 = loc & 255;
        const float* s = wproj + loc;
        float4 v0 = ((const float4*)s)[0], v1 = ((const float4*)s)[1];
        float pv[8] = { v0.x, v1.x, v0.y, v1.y, v0.z, v1.z, v0.w, v1.w };
        #pragma unroll
        for (int i = 0; i < 8; i++)
            g_wprojT[(p0 + i) * 256 + n] = ftf(pv[i]);
    }
}

// ---------------------------------------------------------------------------
// Kernel A (v2): A-RESIDENT Q|K|V GEMM. One CTA per 128 rows computes all
// 768 outputs. A staged once (rounded + permuted, 8 k-planes of 128x36);
// weights streamed per-kb through a double buffer. 512 thr = 16 warps of
// 32x64. Zero CVT in the mainloop.
// ---------------------------------------------------------------------------
#define APL    (128 * 36)          // floats per A k-plane (4608)
#define A_TOT  (8 * APL)           // 36864 floats
#define BT2    (256 * 36)          // B tile floats (9216)
#define QKV2_SMEM ((A_TOT + 2 * BT2) * 4)   // 221184 B

__global__ __launch_bounds__(512, 1) void qkv_mma2(
    const float* __restrict__ x, const float* __restrict__ query)
{
    extern __shared__ float sm[];
    const int tid = threadIdx.x;
    const int p   = blockIdx.x;            // 128-row tile (window pair)
    const int lane = tid & 31, w = tid >> 5;
    const int wm = (w >> 2) * 32;           // 4 m-tiles of 32
    const int wn = (w & 3) * 64;            // 4 n-tiles of 64
    const int gq = lane >> 2, tg = lane & 3;
    const long row0 = (long)p * 128;

    // B load assignment: 2 threads per 32-float row
    const int ldrB = tid >> 1, ldcB = (tid & 1) << 4;
    uint32_t smem_base = (uint32_t)__cvta_generic_to_shared(sm);
    uint32_t b_dst0 = smem_base + (uint32_t)(A_TOT + ldrB * 36 + ldcB) * 4;

    for (int chunk = 0; chunk < 3; ++chunk) {
        // ---- stage A (query for chunks 0-1, x for chunk 2): round + permute
        if (chunk == 0 || chunk == 2) {
            __syncthreads();   // prior chunk's mma must be done reading A
            const float* Ain = (chunk == 0) ? query : x;
            #pragma unroll 1
            for (int it = 0; it < 8; ++it) {
                int idx = it * 512 + tid;       // (row, 8-float group)
                int r = idx >> 5, grp = idx & 31;
                int win = p * 2 + (r >> 6), s = r & 63;
                int b = win >> 8, g = win & 255;
                int n = ((g >> 4) * 8 + (s >> 3)) * 128 + (g & 15) * 8 + (s & 7);
                const float4* sp = (const float4*)(Ain + ((long)b * NTOK + n) * 256 + grp * 8);
                float4 v0 = sp[0], v1 = sp[1];
                float* dst = sm + (grp >> 2) * APL + r * 36 + (grp & 3) * 8;
                ((float4*)dst)[0] = make_float4(ftf(v0.x), ftf(v1.x), ftf(v0.y), ftf(v1.y));
                ((float4*)dst)[1] = make_float4(ftf(v0.z), ftf(v1.z), ftf(v0.w), ftf(v1.w));
            }
            __syncthreads();
        }
        const float* Wt = (chunk == 0) ? g_wqk : (chunk == 1 ? g_wqk + 256 * 256 : g_wv);
        const int dstcol = chunk * 256;

        // preload kb0 -> buf0
        {
            const float* bs = Wt + (long)ldrB * 256 + ldcB;
            #pragma unroll
            for (int i = 0; i < 4; i++) CPA16(b_dst0 + i * 16, bs + i * 4);
            CP_COMMIT();
        }

        float acc[2][8][4];
        #pragma unroll
        for (int mt = 0; mt < 2; mt++)
            #pragma unroll
            for (int nt = 0; nt < 8; nt++)
                #pragma unroll
                for (int q = 0; q < 4; q++) acc[mt][nt][q] = 0.f;

        for (int kb = 0; kb < 8; ++kb) {
            CP_WAIT0();
            __syncthreads();
            if (kb < 7) {
                uint32_t boff = (uint32_t)(((kb + 1) & 1) * BT2 * 4);
                const float* bs = Wt + (long)ldrB * 256 + (kb + 1) * 32 + ldcB;
                #pragma unroll
                for (int i = 0; i < 4; i++) CPA16(b_dst0 + boff + i * 16, bs + i * 4);
                CP_COMMIT();
            }
            const float* sA = sm + kb * APL;
            const float* sB = sm + A_TOT + (kb & 1) * BT2;

            #pragma unroll
            for (int ks = 0; ks < 4; ++ks) {
                const int k0p = ks * 8 + 2 * tg;    // permuted positions
                uint32_t af[2][4];
                #pragma unroll
                for (int mt = 0; mt < 2; mt++) {
                    const int r0 = wm + mt * 16;
                    float2 lo = *(const float2*)&sA[(r0 + gq)     * 36 + k0p];
                    float2 hi = *(const float2*)&sA[(r0 + gq + 8) * 36 + k0p];
                    af[mt][0] = __float_as_uint(lo.x);
                    af[mt][1] = __float_as_uint(hi.x);
                    af[mt][2] = __float_as_uint(lo.y);
                    af[mt][3] = __float_as_uint(hi.y);
                }
                #pragma unroll
                for (int nt = 0; nt < 8; nt++) {
                    float2 bv = *(const float2*)&sB[(wn + nt * 8 + gq) * 36 + k0p];
                    uint32_t b0 = __float_as_uint(bv.x);
                    uint32_t b1 = __float_as_uint(bv.y);
                    mma_tf32(acc[0][nt], af[0][0], af[0][1], af[0][2], af[0][3], b0, b1);
                    mma_tf32(acc[1][nt], af[1][0], af[1][1], af[1][2], af[1][3], b0, b1);
                }
            }
        }

        // epilogue: natural out channels (2tg,2tg+1) -> permuted pos (pb,pb+2)
        const int pb = (tg & 1) * 4 + (tg >> 1);
        #pragma unroll
        for (int mt = 0; mt < 2; mt++) {
            #pragma unroll
            for (int nt = 0; nt < 8; nt++) {
                const int gb = dstcol + wn + nt * 8;
                const long r1 = row0 + wm + mt * 16 + gq;
                g_qkv[r1 * QKVW + gb + pb]           = ftf(acc[mt][nt][0]);
                g_qkv[r1 * QKVW + gb + pb + 2]       = ftf(acc[mt][nt][1]);
                g_qkv[(r1 + 8) * QKVW + gb + pb]     = ftf(acc[mt][nt][2]);
                g_qkv[(r1 + 8) * QKVW + gb + pb + 2] = ftf(acc[mt][nt][3]);
            }
        }
    }
}

// ---------------------------------------------------------------------------
// Kernel B: FUSED attention + output projection (R9, verified passing).
// One block per (window, q-half). 256 thr, warp = head.
// ---------------------------------------------------------------------------
#define PL2 2116
#define RS  66
#define OTS 260
#define OFF_WPRE  (8 * PL2)
#define OFF_WPOST (OFF_WPRE + 64)
#define OFF_RSUM  (OFF_WPRE + 128)
#define OFF_OT    (OFF_RSUM + 256)
#define SMEM_ATTN_BYTES ((OFF_OT + 32 * OTS) * 4)   // 102528 B

__global__ __launch_bounds__(256) void attn_fused(
    const float* __restrict__ W_pre, const float* __restrict__ W_post,
    const float* __restrict__ b_proj, float* __restrict__ out)
{
    extern __shared__ float sm[];
    float* s_attn  = sm;
    float* s_wpre  = sm + OFF_WPRE;
    float* s_wpost = sm + OFF_WPOST;
    float* s_rsum  = sm + OFF_RSUM;
    float* s_ot    = sm + OFF_OT;

    const int tid  = threadIdx.x;
    const int lane = tid & 31;
    const int h    = tid >> 5;
    const int gq = lane >> 2, tg = lane & 3;
    const int h32 = h * 32;
    const int win = blockIdx.x >> 1;
    const int qb  = (blockIdx.x & 1) * 32;
    const long rowbase = (long)win * 64;
    const float* gq_base = g_qkv + rowbase * QKVW;

    if (tid < 64) { s_wpre[tid] = W_pre[tid]; s_wpost[tid] = W_post[tid]; }

    // ---- scores: S_h = Q_h @ K_h^T  (M=32, N=64, K=32) — direct LDG ----
    float acc[2][8][4];
    #pragma unroll
    for (int mt = 0; mt < 2; mt++)
        #pragma unroll
        for (int nt = 0; nt < 8; nt++)
            #pragma unroll
            for (int q = 0; q < 4; q++) acc[mt][nt][q] = 0.f;

    #pragma unroll
    for (int ks = 0; ks < 4; ++ks) {
        const int k0p = h32 + ks * 8 + 2 * tg;
        uint32_t a[2][4];
        #pragma unroll
        for (int mt = 0; mt < 2; mt++) {
            const int r0 = qb + mt * 16;
            float2 lo = *(const float2*)(gq_base + (long)(r0 + gq)     * QKVW + k0p);
            float2 hi = *(const float2*)(gq_base + (long)(r0 + gq + 8) * QKVW + k0p);
            a[mt][0] = __float_as_uint(lo.x);
            a[mt][1] = __float_as_uint(hi.x);
            a[mt][2] = __float_as_uint(lo.y);
            a[mt][3] = __float_as_uint(hi.y);
        }
        #pragma unroll
        for (int nt = 0; nt < 8; nt++) {
            float2 bv = *(const float2*)(gq_base + (long)(nt * 8 + gq) * QKVW + 256 + k0p);
            uint32_t b0 = __float_as_uint(bv.x);
            uint32_t b1 = __float_as_uint(bv.y);
            #pragma unroll
            for (int mt = 0; mt < 2; mt++)
                mma_tf32(acc[mt][nt], a[mt][0], a[mt][1], a[mt][2], a[mt][3], b0, b1);
        }
    }

    const float scale = 0.17677669529663687f;
    float* pl = s_attn + h * PL2;
    #pragma unroll
    for (int mt = 0; mt < 2; mt++) {
        #pragma unroll
        for (int nt = 0; nt < 8; nt++) {
            const int q0 = mt * 16 + gq, c = nt * 8 + 2 * tg;
            *(float2*)&pl[q0 * RS + c] =
                make_float2(acc[mt][nt][0] * scale, acc[mt][nt][1] * scale);
            *(float2*)&pl[(q0 + 8) * RS + c] =
                make_float2(acc[mt][nt][2] * scale, acc[mt][nt][3] * scale);
        }
    }
    __syncthreads();

    // ---- pre-mix + exp ----
    #pragma unroll 1
    for (int i = 0; i < 8; i++) {
        int pidx = tid + (i << 8);
        int q = pidx >> 6, k = pidx & 63;
        float av[8], m[8];
        #pragma unroll
        for (int hh = 0; hh < 8; hh++) av[hh] = s_attn[hh * PL2 + q * RS + k];
        #pragma unroll
        for (int hh = 0; hh < 8; hh++) {
            float s = 0.f;
            #pragma unroll
            for (int h2 = 0; h2 < 8; h2++) s += av[h2] * s_wpre[hh * 8 + h2];
            m[hh] = __expf(s);
        }
        #pragma unroll
        for (int hh = 0; hh < 8; hh++) s_attn[hh * PL2 + q * RS + k] = m[hh];
    }
    __syncthreads();

    // ---- softmax denominator ----
    {
        int q = tid >> 3, hh = tid & 7;
        float s = 0.f;
        #pragma unroll 8
        for (int k = 0; k < 64; k++) s += s_attn[hh * PL2 + q * RS + k];
        s_rsum[tid] = 1.0f / s;
    }
    __syncthreads();

    // ---- normalize + post-mix ----
    #pragma unroll 1
    for (int i = 0; i < 8; i++) {
        int pidx = tid + (i << 8);
        int q = pidx >> 6, k = pidx & 63;
        float av[8], m[8];
        #pragma unroll
        for (int hh = 0; hh < 8; hh++)
            av[hh] = s_attn[hh * PL2 + q * RS + k] * s_rsum[q * 8 + hh];
        #pragma unroll
        for (int hh = 0; hh < 8; hh++) {
            float s = 0.f;
            #pragma unroll
            for (int h2 = 0; h2 < 8; h2++) s += av[h2] * s_wpost[hh * 8 + h2];
            m[hh] = s;
        }
        #pragma unroll
        for (int hh = 0; hh < 8; hh++) s_attn[hh * PL2 + q * RS + k] = m[hh];
    }
    __syncthreads();

    // ---- O_h = A_h @ V_h (M=32, N=32, K=64) — V direct LDG (rounded) ----
    float acc2[2][4][4];
    #pragma unroll
    for (int mt = 0; mt < 2; mt++)
        #pragma unroll
        for (int nt = 0; nt < 4; nt++)
            #pragma unroll
            for (int q = 0; q < 4; q++) acc2[mt][nt][q] = 0.f;

    #pragma unroll
    for (int ks = 0; ks < 8; ++ks) {
        const int k0 = ks * 8;
        uint32_t a[2][4];
        #pragma unroll
        for (int mt = 0; mt < 2; mt++) {
            const int r0 = mt * 16;
            a[mt][0] = f2tf(pl[(r0 + gq)     * RS + k0 + tg]);
            a[mt][1] = f2tf(pl[(r0 + gq + 8) * RS + k0 + tg]);
            a[mt][2] = f2tf(pl[(r0 + gq)     * RS + k0 + tg + 4]);
            a[mt][3] = f2tf(pl[(r0 + gq + 8) * RS + k0 + tg + 4]);
        }
        #pragma unroll
        for (int nt = 0; nt < 4; nt++) {
            const int nb = nt * 8;
            uint32_t b0 = __float_as_uint(
                gq_base[(long)(k0 + tg)     * QKVW + 512 + h32 + nb + gq]);
            uint32_t b1 = __float_as_uint(
                gq_base[(long)(k0 + tg + 4) * QKVW + 512 + h32 + nb + gq]);
            #pragma unroll
            for (int mt = 0; mt < 2; mt++)
                mma_tf32(acc2[mt][nt], a[mt][0], a[mt][1], a[mt][2], a[mt][3], b0, b1);
        }
    }

    // ---- O to smem (rounded; already position space) ----
    #pragma unroll
    for (int mt = 0; mt < 2; mt++) {
        #pragma unroll
        for (int nt = 0; nt < 4; nt++) {
            const int col = h32 + nt * 8 + 2 * tg;
            const int r0 = mt * 16 + gq;
            *(float2*)&s_ot[r0 * OTS + col] =
                make_float2(ftf(acc2[mt][nt][0]), ftf(acc2[mt][nt][1]));
            *(float2*)&s_ot[(r0 + 8) * OTS + col] =
                make_float2(ftf(acc2[mt][nt][2]), ftf(acc2[mt][nt][3]));
        }
    }
    __syncthreads();

    // ---- out = O @ W_proj^T + b_proj  (M=32, N=32/warp, K=256) ----
    float pacc[2][4][4];
    #pragma unroll
    for (int mt = 0; mt < 2; mt++)
        #pragma unroll
        for (int nt = 0; nt < 4; nt++)
            #pragma unroll
            for (int q = 0; q < 4; q++) pacc[mt][nt][q] = 0.f;

    #pragma unroll 2
    for (int ks = 0; ks < 32; ++ks) {
        const int k0p = ks * 8 + 2 * tg;
        uint32_t a[2][4];
        #pragma unroll
        for (int mt = 0; mt < 2; mt++) {
            const int r0 = mt * 16;
            float2 lo = *(const float2*)&s_ot[(r0 + gq)     * OTS + k0p];
            float2 hi = *(const float2*)&s_ot[(r0 + gq + 8) * OTS + k0p];
            a[mt][0] = __float_as_uint(lo.x);
            a[mt][1] = __float_as_uint(hi.x);
            a[mt][2] = __float_as_uint(lo.y);
            a[mt][3] = __float_as_uint(hi.y);
        }
        #pragma unroll
        for (int nt = 0; nt < 4; nt++) {
            const int wcol = h32 + nt * 8 + gq;
            uint32_t b0 = __float_as_uint(g_wprojT[(long)k0p * 256 + wcol]);
            uint32_t b1 = __float_as_uint(g_wprojT[(long)(k0p + 1) * 256 + wcol]);
            #pragma unroll
            for (int mt = 0; mt < 2; mt++)
                mma_tf32(pacc[mt][nt], a[mt][0], a[mt][1], a[mt][2], a[mt][3], b0, b1);
        }
    }

    // ---- epilogue: unwindow rows, add bias, store ----
    const int bidx = win >> 8, g = win & 255;
    #pragma unroll
    for (int mt = 0; mt < 2; mt++) {
        #pragma unroll
        for (int nt = 0; nt < 4; nt++) {
            const int col = h32 + nt * 8 + 2 * tg;
            const float2 bv = *(const float2*)(b_proj + col);
            #pragma unroll
            for (int half = 0; half < 2; half++) {
                const int s = qb + mt * 16 + gq + half * 8;
                const int i = (g >> 4) * 8 + (s >> 3);
                const int j = (g & 15) * 8 + (s & 7);
                const long orow = (long)bidx * NTOK + i * 128 + j;
                *(float2*)(out + orow * NC + col) =
                    make_float2(pacc[mt][nt][half * 2]     + bv.x,
                                pacc[mt][nt][half * 2 + 1] + bv.y);
            }
        }
    }
}

// ---------------------------------------------------------------------------
extern "C" void kernel_launch(void* const* d_in, const int* in_sizes, int n_in,
                              void* d_out, int out_size)
{
    const float* x      = (const float*)d_in[0];
    const float* query  = (const float*)d_in[1];
    const float* W_qk   = (const float*)d_in[2];
    const float* W_v    = (const float*)d_in[3];
    const float* W_proj = (const float*)d_in[4];
    const float* b_proj = (const float*)d_in[5];
    const float* W_pre  = (const float*)d_in[6];
    const float* W_post = (const float*)d_in[7];
    float* out = (float*)d_out;

    cudaFuncSetAttribute(qkv_mma2, cudaFuncAttributeMaxDynamicSharedMemorySize, QKV2_SMEM);
    cudaFuncSetAttribute(attn_fused, cudaFuncAttributeMaxDynamicSharedMemorySize, SMEM_ATTN_BYTES);

    cvt_weights<<<128, 256>>>(W_qk, W_v, W_proj);
    qkv_mma2<<<1024, 512, QKV2_SMEM>>>(x, query);
    attn_fused<<<NWIN * 2, 256, SMEM_ATTN_BYTES>>>(W_pre, W_post, b_proj, out);
}

// round 11
// speedup vs baseline: 1.1234x; 1.1234x over previous
#include <cuda_runtime.h>
#include <cstdint>

// Problem constants
#define NB    8
#define NTOK  16384
#define NC    256
#define NWIN  2048    // B * (16x16 windows)
#define QKVW  768     // q(256) | k(256) | v(256)

// g_qkv channel dims stored PERMUTED within 8-groups:
// position p holds channel c(p) = (p&1)*4 + (p>>1)   (order 0,4,1,5,2,6,3,7)
__device__ float g_qkv[(size_t)NWIN * 64 * QKVW];
__device__ float g_wqk[512 * 256];     // rounded + permuted cols (rows natural)
__device__ float g_wv[256 * 256];
__device__ float g_wproj[256 * 256];

// ---------------------------------------------------------------------------
__device__ __forceinline__ uint32_t f2tf(float f) {
    uint32_t u;
    asm("cvt.rna.tf32.f32 %0, %1;" : "=r"(u) : "f"(f));
    return u;
}
__device__ __forceinline__ float ftf(float f) {
    return __uint_as_float(f2tf(f));
}
__device__ __forceinline__ void mma_tf32(float c[4],
    uint32_t a0, uint32_t a1, uint32_t a2, uint32_t a3,
    uint32_t b0, uint32_t b1)
{
    asm volatile(
        "mma.sync.aligned.m16n8k8.row.col.f32.tf32.tf32.f32 "
        "{%0,%1,%2,%3},{%4,%5,%6,%7},{%8,%9},{%0,%1,%2,%3};"
        : "+f"(c[0]), "+f"(c[1]), "+f"(c[2]), "+f"(c[3])
        : "r"(a0), "r"(a1), "r"(a2), "r"(a3), "r"(b0), "r"(b1));
}
#define CPA16(dst, src) \
    asm volatile("cp.async.cg.shared.global [%0],[%1],16;" :: "r"(dst), "l"(src))
#define CP_COMMIT() asm volatile("cp.async.commit_group;")
#define CP_WAIT0()  asm volatile("cp.async.wait_group 0;" ::: "memory")

// qkv GEMM tiles: BM=128, BN=64, BK=32, 256 threads (8 warps of 32x32)
#define TS      36
#define ATILE_F (128 * TS)
#define BTILE_F (64 * TS)
#define BUF2_F  (ATILE_F + BTILE_F)
#define SMEM_G2 (2 * BUF2_F * 4)      // 55296 B -> 4 CTAs/SM

// ---------------------------------------------------------------------------
// Weights: round to tf32 + permute 8-groups (rows natural)
// ---------------------------------------------------------------------------
__global__ __launch_bounds__(256) void cvt_weights(
    const float* __restrict__ wqk, const float* __restrict__ wv,
    const float* __restrict__ wproj)
{
    const int t = blockIdx.x * 256 + threadIdx.x;
    const int off = t * 8;
    const float* s; float* d;
    if (off < 131072)      { s = wqk + off;           d = g_wqk + off; }
    else if (off < 196608) { s = wv + off - 131072;   d = g_wv + off - 131072; }
    else                   { s = wproj + off - 196608; d = g_wproj + off - 196608; }
    float4 v0 = ((const float4*)s)[0], v1 = ((const float4*)s)[1];
    ((float4*)d)[0] = make_float4(ftf(v0.x), ftf(v1.x), ftf(v0.y), ftf(v1.y));
    ((float4*)d)[1] = make_float4(ftf(v0.z), ftf(v1.z), ftf(v0.w), ftf(v1.w));
}

// ---------------------------------------------------------------------------
// Kernel A: Q|K|V GEMM (R7 config: 128x64 tile, 4 CTAs/SM).
// GRID SWAPPED: cb = blockIdx.x (fast), p = blockIdx.y -> the 12 CTAs
// sharing one A tile are schedule-adjacent => A reads hit L2.
// ---------------------------------------------------------------------------
__global__ __launch_bounds__(256, 4) void qkv_mma(
    const float* __restrict__ x, const float* __restrict__ query)
{
    extern __shared__ float sm[];
    const int tid = threadIdx.x;
    const int cb  = blockIdx.x;     // 0..11  (fast dim: co-schedule same p)
    const int p   = blockIdx.y;     // 0..1023, 128-row tile

    const float* in = (cb < 8) ? query : x;
    const float* Wt = (cb < 8) ? (g_wqk + (long)cb * 64 * 256)
                               : (g_wv  + (long)(cb - 8) * 64 * 256);
    const int dstcol = (cb < 8) ? cb * 64 : 512 + (cb - 8) * 64;

    const int ldrA = tid >> 1, ldcA = (tid & 1) << 4;
    const int ldrB = tid >> 2, ldcB = (tid & 3) << 3;
    int win = p * 2 + (ldrA >> 6);
    int s   = ldrA & 63;
    int b   = win >> 8, g = win & 255;
    int n   = ((g >> 4) * 8 + (s >> 3)) * 128 + (g & 15) * 8 + (s & 7);
    const float* a_src0 = in + ((long)b * NTOK + n) * 256 + ldcA;
    const float* b_src0 = Wt + (long)ldrB * 256 + ldcB;

    uint32_t smem_base = (uint32_t)__cvta_generic_to_shared(sm);
    uint32_t a_dst0 = smem_base + (uint32_t)(ldrA * TS + ldcA) * 4;
    uint32_t b_dst0 = smem_base + (uint32_t)(ATILE_F + ldrB * TS + ldcB) * 4;

    const int lane = tid & 31, w = tid >> 5;
    const int wm = (w >> 1) * 32;
    const int wn = (w & 1) * 32;
    const int gq = lane >> 2, tg = lane & 3;

    float acc[2][4][4];
    #pragma unroll
    for (int mt = 0; mt < 2; mt++)
        #pragma unroll
        for (int nt = 0; nt < 4; nt++)
            #pragma unroll
            for (int q = 0; q < 4; q++) acc[mt][nt][q] = 0.f;

    {
        #pragma unroll
        for (int i = 0; i < 4; i++) CPA16(a_dst0 + i * 16, a_src0 + i * 4);
        #pragma unroll
        for (int i = 0; i < 2; i++) CPA16(b_dst0 + i * 16, b_src0 + i * 4);
        CP_COMMIT();
    }

    for (int kb = 0; kb < 8; ++kb) {
        CP_WAIT0();
        __syncthreads();
        if (kb < 7) {
            uint32_t off = (uint32_t)(((kb + 1) & 1) * BUF2_F * 4);
            const float* as = a_src0 + (kb + 1) * 32;
            const float* bs = b_src0 + (kb + 1) * 32;
            #pragma unroll
            for (int i = 0; i < 4; i++) CPA16(a_dst0 + off + i * 16, as + i * 4);
            #pragma unroll
            for (int i = 0; i < 2; i++) CPA16(b_dst0 + off + i * 16, bs + i * 4);
            CP_COMMIT();
        }
        const float* sA = sm + (kb & 1) * BUF2_F;
        const float* sB = sA + ATILE_F;

        #pragma unroll
        for (int ks = 0; ks < 4; ++ks) {
            const int k0n = ks * 8;            // natural channels (A)
            const int k0p = ks * 8 + 2 * tg;   // permuted positions (B)
            uint32_t af[2][4];
            #pragma unroll
            for (int mt = 0; mt < 2; mt++) {
                const int r0 = wm + mt * 16;
                af[mt][0] = f2tf(sA[(r0 + gq)     * TS + k0n + tg]);
                af[mt][1] = f2tf(sA[(r0 + gq + 8) * TS + k0n + tg]);
                af[mt][2] = f2tf(sA[(r0 + gq)     * TS + k0n + tg + 4]);
                af[mt][3] = f2tf(sA[(r0 + gq + 8) * TS + k0n + tg + 4]);
            }
            #pragma unroll
            for (int nt = 0; nt < 4; nt++) {
                float2 bv = *(const float2*)&sB[(wn + nt * 8 + gq) * TS + k0p];
                uint32_t b0 = __float_as_uint(bv.x);
                uint32_t b1 = __float_as_uint(bv.y);
                mma_tf32(acc[0][nt], af[0][0], af[0][1], af[0][2], af[0][3], b0, b1);
                mma_tf32(acc[1][nt], af[1][0], af[1][1], af[1][2], af[1][3], b0, b1);
            }
        }
    }

    const long row0 = (long)p * 128;
    const int pb = (tg & 1) * 4 + (tg >> 1);
    #pragma unroll
    for (int mt = 0; mt < 2; mt++) {
        #pragma unroll
        for (int nt = 0; nt < 4; nt++) {
            const int gb = dstcol + wn + nt * 8;
            const long r1 = row0 + wm + mt * 16 + gq;
            g_qkv[r1 * QKVW + gb + pb]           = ftf(acc[mt][nt][0]);
            g_qkv[r1 * QKVW + gb + pb + 2]       = ftf(acc[mt][nt][1]);
            g_qkv[(r1 + 8) * QKVW + gb + pb]     = ftf(acc[mt][nt][2]);
            g_qkv[(r1 + 8) * QKVW + gb + pb + 2] = ftf(acc[mt][nt][3]);
        }
    }
}

// ---------------------------------------------------------------------------
// Kernel B: attention (R7, verified best): block per (window, q-half),
// 256 thr, warp = head. Q/K/V fragments via direct LDG from g_qkv.
// ---------------------------------------------------------------------------
#define PL2 2116
#define RS  66
#define OFF_WPRE  (8 * PL2)
#define OFF_WPOST (OFF_WPRE + 64)
#define OFF_RSUM  (OFF_WPRE + 128)
#define SMEM_ATTN_BYTES ((OFF_RSUM + 256) * 4)

__global__ __launch_bounds__(256) void attn_kernel(
    const float* __restrict__ W_pre, const float* __restrict__ W_post)
{
    extern __shared__ float sm[];
    float* s_attn  = sm;
    float* s_wpre  = sm + OFF_WPRE;
    float* s_wpost = sm + OFF_WPOST;
    float* s_rsum  = sm + OFF_RSUM;

    const int tid  = threadIdx.x;
    const int lane = tid & 31;
    const int h    = tid >> 5;
    const int gq = lane >> 2, tg = lane & 3;
    const int h32 = h * 32;
    const int win = blockIdx.x >> 1;
    const int qb  = (blockIdx.x & 1) * 32;
    const long rowbase = (long)win * 64;
    const float* gq_base = g_qkv + rowbase * QKVW;

    if (tid < 64) { s_wpre[tid] = W_pre[tid]; s_wpost[tid] = W_post[tid]; }

    float acc[2][8][4];
    #pragma unroll
    for (int mt = 0; mt < 2; mt++)
        #pragma unroll
        for (int nt = 0; nt < 8; nt++)
            #pragma unroll
            for (int q = 0; q < 4; q++) acc[mt][nt][q] = 0.f;

    #pragma unroll
    for (int ks = 0; ks < 4; ++ks) {
        const int k0p = h32 + ks * 8 + 2 * tg;
        uint32_t a[2][4];
        #pragma unroll
        for (int mt = 0; mt < 2; mt++) {
            const int r0 = qb + mt * 16;
            float2 lo = *(const float2*)(gq_base + (long)(r0 + gq)     * QKVW + k0p);
            float2 hi = *(const float2*)(gq_base + (long)(r0 + gq + 8) * QKVW + k0p);
            a[mt][0] = __float_as_uint(lo.x);
            a[mt][1] = __float_as_uint(hi.x);
            a[mt][2] = __float_as_uint(lo.y);
            a[mt][3] = __float_as_uint(hi.y);
        }
        #pragma unroll
        for (int nt = 0; nt < 8; nt++) {
            float2 bv = *(const float2*)(gq_base + (long)(nt * 8 + gq) * QKVW + 256 + k0p);
            uint32_t b0 = __float_as_uint(bv.x);
            uint32_t b1 = __float_as_uint(bv.y);
            #pragma unroll
            for (int mt = 0; mt < 2; mt++)
                mma_tf32(acc[mt][nt], a[mt][0], a[mt][1], a[mt][2], a[mt][3], b0, b1);
        }
    }

    const float scale = 0.17677669529663687f;
    float* pl = s_attn + h * PL2;
    #pragma unroll
    for (int mt = 0; mt < 2; mt++) {
        #pragma unroll
        for (int nt = 0; nt < 8; nt++) {
            const int q0 = mt * 16 + gq, c = nt * 8 + 2 * tg;
            *(float2*)&pl[q0 * RS + c] =
                make_float2(acc[mt][nt][0] * scale, acc[mt][nt][1] * scale);
            *(float2*)&pl[(q0 + 8) * RS + c] =
                make_float2(acc[mt][nt][2] * scale, acc[mt][nt][3] * scale);
        }
    }
    __syncthreads();

    #pragma unroll 1
    for (int i = 0; i < 8; i++) {
        int pidx = tid + (i << 8);
        int q = pidx >> 6, k = pidx & 63;
        float av[8], m[8];
        #pragma unroll
        for (int hh = 0; hh < 8; hh++) av[hh] = s_attn[hh * PL2 + q * RS + k];
        #pragma unroll
        for (int hh = 0; hh < 8; hh++) {
            float s = 0.f;
            #pragma unroll
            for (int h2 = 0; h2 < 8; h2++) s += av[h2] * s_wpre[hh * 8 + h2];
            m[hh] = __expf(s);
        }
        #pragma unroll
        for (int hh = 0; hh < 8; hh++) s_attn[hh * PL2 + q * RS + k] = m[hh];
    }
    __syncthreads();

    {
        int q = tid >> 3, hh = tid & 7;
        float s = 0.f;
        #pragma unroll 8
        for (int k = 0; k < 64; k++) s += s_attn[hh * PL2 + q * RS + k];
        s_rsum[tid] = 1.0f / s;
    }
    __syncthreads();

    #pragma unroll 1
    for (int i = 0; i < 8; i++) {
        int pidx = tid + (i << 8);
        int q = pidx >> 6, k = pidx & 63;
        float av[8], m[8];
        #pragma unroll
        for (int hh = 0; hh < 8; hh++)
            av[hh] = s_attn[hh * PL2 + q * RS + k] * s_rsum[q * 8 + hh];
        #pragma unroll
        for (int hh = 0; hh < 8; hh++) {
            float s = 0.f;
            #pragma unroll
            for (int h2 = 0; h2 < 8; h2++) s += av[h2] * s_wpost[hh * 8 + h2];
            m[hh] = s;
        }
        #pragma unroll
        for (int hh = 0; hh < 8; hh++) s_attn[hh * PL2 + q * RS + k] = m[hh];
    }
    __syncthreads();

    float acc2[2][4][4];
    #pragma unroll
    for (int mt = 0; mt < 2; mt++)
        #pragma unroll
        for (int nt = 0; nt < 4; nt++)
            #pragma unroll
            for (int q = 0; q < 4; q++) acc2[mt][nt][q] = 0.f;

    #pragma unroll
    for (int ks = 0; ks < 8; ++ks) {
        const int k0 = ks * 8;
        uint32_t a[2][4];
        #pragma unroll
        for (int mt = 0; mt < 2; mt++) {
            const int r0 = mt * 16;
            a[mt][0] = f2tf(pl[(r0 + gq)     * RS + k0 + tg]);
            a[mt][1] = f2tf(pl[(r0 + gq + 8) * RS + k0 + tg]);
            a[mt][2] = f2tf(pl[(r0 + gq)     * RS + k0 + tg + 4]);
            a[mt][3] = f2tf(pl[(r0 + gq + 8) * RS + k0 + tg + 4]);
        }
        #pragma unroll
        for (int nt = 0; nt < 4; nt++) {
            const int nb = nt * 8;
            uint32_t b0 = __float_as_uint(
                gq_base[(long)(k0 + tg)     * QKVW + 512 + h32 + nb + gq]);
            uint32_t b1 = __float_as_uint(
                gq_base[(long)(k0 + tg + 4) * QKVW + 512 + h32 + nb + gq]);
            #pragma unroll
            for (int mt = 0; mt < 2; mt++)
                mma_tf32(acc2[mt][nt], a[mt][0], a[mt][1], a[mt][2], a[mt][3], b0, b1);
        }
    }

    #pragma unroll
    for (int mt = 0; mt < 2; mt++) {
        #pragma unroll
        for (int nt = 0; nt < 4; nt++) {
            const int col = h32 + nt * 8 + 2 * tg;
            const long r1 = rowbase + qb + mt * 16 + gq;
            *(float2*)(g_qkv + r1 * QKVW + col) =
                make_float2(ftf(acc2[mt][nt][0]), ftf(acc2[mt][nt][1]));
            *(float2*)(g_qkv + (r1 + 8) * QKVW + col) =
                make_float2(ftf(acc2[mt][nt][2]), ftf(acc2[mt][nt][3]));
        }
    }
}

// ---------------------------------------------------------------------------
// Kernel C: proj (R6/R8 BN=128 config, zero CVT). GRID SWAPPED:
// colb = blockIdx.x (fast), row-tile = blockIdx.y -> the 2 CTAs sharing a
// row-gather tile co-run (second read hits L2).
// ---------------------------------------------------------------------------
#define PTS     36
#define PTILE_F (128 * PTS)
#define PBUF_F  (2 * PTILE_F)
#define SMEM_PROJ (2 * PBUF_F * 4)

__global__ __launch_bounds__(256) void proj_mma(
    const float* __restrict__ b_proj, float* __restrict__ out)
{
    extern __shared__ float sm[];
    const int tid = threadIdx.x;
    const long row0 = (long)blockIdx.y * 128;
    const int colb = blockIdx.x * 128;

    const int ldr = tid >> 1;
    const int ldc = (tid & 1) << 4;
    long row = row0 + ldr;
    int b = (int)(row >> 14);
    int n = (int)(row & 16383);
    int i = n >> 7, j = n & 127;
    int srcrow = ((b << 8) + (i >> 3) * 16 + (j >> 3)) * 64 + (i & 7) * 8 + (j & 7);
    const float* a_src0 = g_qkv + (long)srcrow * QKVW + ldc;
    const float* b_src0 = g_wproj + (long)(colb + ldr) * 256 + ldc;

    uint32_t smem_base = (uint32_t)__cvta_generic_to_shared(sm);
    uint32_t a_dst0 = smem_base + (uint32_t)(ldr * PTS + ldc) * 4;
    uint32_t b_dst0 = a_dst0 + PTILE_F * 4;

    const int lane = tid & 31, w = tid >> 5;
    const int wm = (w >> 1) * 32;
    const int wn = (w & 1) * 64;
    const int gq = lane >> 2, tg = lane & 3;

    float acc[2][8][4];
    #pragma unroll
    for (int mt = 0; mt < 2; mt++)
        #pragma unroll
        for (int nt = 0; nt < 8; nt++)
            #pragma unroll
            for (int q = 0; q < 4; q++) acc[mt][nt][q] = 0.f;

    {
        #pragma unroll
        for (int k = 0; k < 4; k++) CPA16(a_dst0 + k * 16, a_src0 + k * 4);
        #pragma unroll
        for (int k = 0; k < 4; k++) CPA16(b_dst0 + k * 16, b_src0 + k * 4);
        CP_COMMIT();
    }

    for (int kb = 0; kb < 8; ++kb) {
        CP_WAIT0();
        __syncthreads();
        if (kb < 7) {
            uint32_t off = (uint32_t)(((kb + 1) & 1) * PBUF_F * 4);
            const float* as = a_src0 + (kb + 1) * 32;
            const float* bs = b_src0 + (kb + 1) * 32;
            #pragma unroll
            for (int k = 0; k < 4; k++) CPA16(a_dst0 + off + k * 16, as + k * 4);
            #pragma unroll
            for (int k = 0; k < 4; k++) CPA16(b_dst0 + off + k * 16, bs + k * 4);
            CP_COMMIT();
        }
        const float* sA = sm + (kb & 1) * PBUF_F;
        const float* sB = sA + PTILE_F;

        #pragma unroll
        for (int ks = 0; ks < 4; ++ks) {
            const int k0 = ks * 8 + 2 * tg;   // positions (both sides permuted)
            uint32_t af[2][4];
            #pragma unroll
            for (int mt = 0; mt < 2; mt++) {
                const int r0 = wm + mt * 16;
                float2 lo = *(const float2*)&sA[(r0 + gq)     * PTS + k0];
                float2 hi = *(const float2*)&sA[(r0 + gq + 8) * PTS + k0];
                af[mt][0] = __float_as_uint(lo.x);
                af[mt][1] = __float_as_uint(hi.x);
                af[mt][2] = __float_as_uint(lo.y);
                af[mt][3] = __float_as_uint(hi.y);
            }
            #pragma unroll
            for (int nt = 0; nt < 8; nt++) {
                float2 bv = *(const float2*)&sB[(wn + nt * 8 + gq) * PTS + k0];
                uint32_t b0 = __float_as_uint(bv.x);
                uint32_t b1 = __float_as_uint(bv.y);
                mma_tf32(acc[0][nt], af[0][0], af[0][1], af[0][2], af[0][3], b0, b1);
                mma_tf32(acc[1][nt], af[1][0], af[1][1], af[1][2], af[1][3], b0, b1);
            }
        }
    }

    #pragma unroll
    for (int mt = 0; mt < 2; mt++) {
        #pragma unroll
        for (int nt = 0; nt < 8; nt++) {
            const int col = colb + wn + nt * 8 + tg * 2;
            const float2 bv = *(const float2*)(b_proj + col);
            const long r1 = row0 + wm + mt * 16 + gq;
            *(float2*)(out + r1 * NC + col) =
                make_float2(acc[mt][nt][0] + bv.x, acc[mt][nt][1] + bv.y);
            *(float2*)(out + (r1 + 8) * NC + col) =
                make_float2(acc[mt][nt][2] + bv.x, acc[mt][nt][3] + bv.y);
        }
    }
}

// ---------------------------------------------------------------------------
extern "C" void kernel_launch(void* const* d_in, const int* in_sizes, int n_in,
                              void* d_out, int out_size)
{
    const float* x      = (const float*)d_in[0];
    const float* query  = (const float*)d_in[1];
    const float* W_qk   = (const float*)d_in[2];
    const float* W_v    = (const float*)d_in[3];
    const float* W_proj = (const float*)d_in[4];
    const float* b_proj = (const float*)d_in[5];
    const float* W_pre  = (const float*)d_in[6];
    const float* W_post = (const float*)d_in[7];
    float* out = (float*)d_out;

    cudaFuncSetAttribute(qkv_mma, cudaFuncAttributeMaxDynamicSharedMemorySize, SMEM_G2);
    cudaFuncSetAttribute(attn_kernel, cudaFuncAttributeMaxDynamicSharedMemorySize, SMEM_ATTN_BYTES);
    cudaFuncSetAttribute(proj_mma, cudaFuncAttributeMaxDynamicSharedMemorySize, SMEM_PROJ);

    cvt_weights<<<128, 256>>>(W_qk, W_v, W_proj);
    qkv_mma<<<dim3(12, 1024), 256, SMEM_G2>>>(x, query);
    attn_kernel<<<NWIN * 2, 256, SMEM_ATTN_BYTES>>>(W_pre, W_post);
    proj_mma<<<dim3(2, 1024), 256, SMEM_PROJ>>>(b_proj, out);
}